// round 8
// baseline (speedup 1.0000x reference)
#include <cuda_runtime.h>
#include <cstdint>

// out[b,t,a] = start_state[b,a] + (t/255) * patterns[iid[b], t, a]
// B=256, T=256, AD=64 -> 16 float4 per (b,t) row, 1,048,576 float4 total.
//
// R8: best structure (R3: warp LDG/STG) fattened to MLP=8.
// 512 CTAs x 256 threads; each thread: 8 float4 across 8 t-values (stride 16)
// of one batch row. Loads front-batched (8 independent LDG.128 in flight),
// stores batched after. iid/start_state loaded once per thread.

#define B_   256
#define T_   256
#define AD_  64
#define F4_PER_ROW 16
#define TPB  256
#define TPT  8                 // t-values per thread
#define CHUNKS_PER_B 2         // 256 t / (16 trows * 8 iters)

__global__ __launch_bounds__(TPB)
void traj_kernel(const float* __restrict__ start_state,    // [B, 64]
                 const int*   __restrict__ instruction_id, // [B]
                 const float* __restrict__ patterns,       // [V, T, 64]
                 float*       __restrict__ out)            // [B, T, 64]
{
    const unsigned bid   = blockIdx.x;
    const unsigned b     = bid >> 1;          // 2 chunks per batch row
    const unsigned chunk = bid & 1u;
    const unsigned tid   = threadIdx.x;
    const unsigned a4    = tid & 15u;         // float4 slot within 64-float row
    const unsigned trow  = tid >> 4;          // 0..15
    const unsigned t0    = chunk * 128u + trow;

    const int iid = __ldg(&instruction_id[b]);

    const float4 s = __ldg((const float4*)(start_state + (size_t)b * AD_) + a4);

    const float4* __restrict__ pat =
        (const float4*)(patterns + (size_t)iid * T_ * AD_) + a4;
    float4* __restrict__ dst =
        (float4*)(out + (size_t)b * T_ * AD_) + a4;

    // 8 independent pattern loads, front-batched (MLP=8).
    float4 p[TPT];
#pragma unroll
    for (int i = 0; i < TPT; i++) {
        const unsigned t = t0 + (unsigned)i * 16u;
        p[i] = __ldg(pat + t * F4_PER_ROW);
    }

    // FMA + batched stores.
#pragma unroll
    for (int i = 0; i < TPT; i++) {
        const unsigned t = t0 + (unsigned)i * 16u;
        const float prog = (float)t * (1.0f / (float)(T_ - 1));
        float4 r;
        r.x = fmaf(prog, p[i].x, s.x);
        r.y = fmaf(prog, p[i].y, s.y);
        r.z = fmaf(prog, p[i].z, s.z);
        r.w = fmaf(prog, p[i].w, s.w);
        dst[t * F4_PER_ROW] = r;
    }
}

extern "C" void kernel_launch(void* const* d_in, const int* in_sizes, int n_in,
                              void* d_out, int out_size)
{
    const float* start_state    = (const float*)d_in[0];
    const int*   instruction_id = (const int*)  d_in[1];
    const float* patterns       = (const float*)d_in[27];
    float*       out            = (float*)d_out;

    traj_kernel<<<B_ * CHUNKS_PER_B, TPB>>>(start_state, instruction_id, patterns, out);
}

// round 9
// speedup vs baseline: 1.0333x; 1.0333x over previous
#include <cuda_runtime.h>
#include <cstdint>

// out[b,t,a] = start_state[b,a] + (t/255) * patterns[iid[b], t, a]
// B=256, T=256, AD=64 -> each (b,t) row = 64 floats = 8 x 256-bit vectors.
//
// R9: R3 shape (1024 CTAs x 256 thr, 16KB tile/CTA) with sm_100+ 256-bit
// vector memory ops (LDG.E.256 / STG.E.256): 2 loads + 2 stores per thread
// instead of 4+4. Halves LSU issue + L1tex wavefront-queue entries.

#define B_   256
#define T_   256
#define AD_  64
#define V8_PER_ROW 8            // 64 floats / 8
#define TPB  256

struct f8 { float v[8]; };

__device__ __forceinline__ f8 ldg_v8(const float* p) {
    f8 r;
    asm volatile("ld.global.nc.v8.f32 {%0,%1,%2,%3,%4,%5,%6,%7}, [%8];"
                 : "=f"(r.v[0]), "=f"(r.v[1]), "=f"(r.v[2]), "=f"(r.v[3]),
                   "=f"(r.v[4]), "=f"(r.v[5]), "=f"(r.v[6]), "=f"(r.v[7])
                 : "l"(p));
    return r;
}

__device__ __forceinline__ void stg_v8(float* p, const f8& r) {
    asm volatile("st.global.v8.f32 [%0], {%1,%2,%3,%4,%5,%6,%7,%8};"
                 :: "l"(p),
                    "f"(r.v[0]), "f"(r.v[1]), "f"(r.v[2]), "f"(r.v[3]),
                    "f"(r.v[4]), "f"(r.v[5]), "f"(r.v[6]), "f"(r.v[7])
                 : "memory");
}

__global__ __launch_bounds__(TPB)
void traj_kernel(const float* __restrict__ start_state,    // [B, 64]
                 const int*   __restrict__ instruction_id, // [B]
                 const float* __restrict__ patterns,       // [V, T, 64]
                 float*       __restrict__ out)            // [B, T, 64]
{
    const unsigned bid   = blockIdx.x;
    const unsigned b     = bid >> 2;          // 4 chunks of 64 t per batch row
    const unsigned chunk = bid & 3u;
    const unsigned tid   = threadIdx.x;
    const unsigned a8    = tid & 7u;          // 256-bit slot within 64-float row
    const unsigned trow  = tid >> 3;          // 0..31
    const unsigned tbase = chunk * 64u;

    const int iid = __ldg(&instruction_id[b]);

    const f8 s = ldg_v8(start_state + (size_t)b * AD_ + a8 * 8u);

    const float* __restrict__ pat =
        patterns + ((size_t)iid * T_ + tbase) * AD_ + a8 * 8u;
    float* __restrict__ dst =
        out + ((size_t)b * T_ + tbase) * AD_ + a8 * 8u;

    // 2 independent 256-bit loads, front-batched.
    const unsigned t0 = trow;          // local t, iter 0
    const unsigned t1 = trow + 32u;    // local t, iter 1
    f8 p0 = ldg_v8(pat + (size_t)t0 * AD_);
    f8 p1 = ldg_v8(pat + (size_t)t1 * AD_);

    const float prog0 = (float)(tbase + t0) * (1.0f / (float)(T_ - 1));
    const float prog1 = (float)(tbase + t1) * (1.0f / (float)(T_ - 1));

    f8 r0, r1;
#pragma unroll
    for (int i = 0; i < 8; i++) r0.v[i] = fmaf(prog0, p0.v[i], s.v[i]);
#pragma unroll
    for (int i = 0; i < 8; i++) r1.v[i] = fmaf(prog1, p1.v[i], s.v[i]);

    stg_v8(dst + (size_t)t0 * AD_, r0);
    stg_v8(dst + (size_t)t1 * AD_, r1);
}

extern "C" void kernel_launch(void* const* d_in, const int* in_sizes, int n_in,
                              void* d_out, int out_size)
{
    const float* start_state    = (const float*)d_in[0];
    const int*   instruction_id = (const int*)  d_in[1];
    const float* patterns       = (const float*)d_in[27];
    float*       out            = (float*)d_out;

    traj_kernel<<<B_ * 4, TPB>>>(start_state, instruction_id, patterns, out);
}